// round 15
// baseline (speedup 1.0000x reference)
#include <cuda_runtime.h>

#define NPOS 4096   // 16*16*16
#define CCH  64

// ---------------- scratch (device globals; no allocation allowed) ----------
__device__ float g_y1 [CCH*NPOS];
__device__ float g_y2 [CCH*NPOS];
__device__ float g_q  [4*NPOS*16];   // [head][pos][hd], pre-scaled by 0.25
__device__ float g_kT [4*16*NPOS];   // [head][hd][pos]
__device__ float g_v  [4*NPOS*16];   // [head][pos][hd]
__device__ float g_att[4*NPOS*16];   // attention output [head][pos][hd]
__device__ float g_T  [256];         // T[a*16+b] = sigmoid(gamma)^|a-b|

// ---------------- init: decay table --------------------------------------
__global__ void k_init(const float* __restrict__ gamma) {
    __shared__ float P[16];
    if (threadIdx.x == 0) {
        float g = 1.0f / (1.0f + expf(-gamma[0]));
        float p = 1.0f;
        for (int t = 0; t < 16; ++t) { P[t] = p; p *= g; }
    }
    __syncthreads();
    int a = threadIdx.x >> 4, b = threadIdx.x & 15;
    g_T[threadIdx.x] = P[a > b ? a - b : b - a];
}

// ---------------- conv1: 3x3 spatial, pad (0,1,1) -------------------------
// grid (16 d, 8 cogroup), block 256 = (h,w)
__global__ void k_conv_sp(const float* __restrict__ x,
                          const float* __restrict__ w,
                          const float* __restrict__ bias) {
    const int d = blockIdx.x, cog = blockIdx.y;
    __shared__ float ws[4608];                 // 8 co x 64 ci x 9
    for (int i = threadIdx.x; i < 4608; i += 256) ws[i] = w[cog * 4608 + i];
    __syncthreads();
    const int h = threadIdx.x >> 4, ww = threadIdx.x & 15;
    float acc[8];
#pragma unroll
    for (int co = 0; co < 8; ++co) acc[co] = __ldg(&bias[cog * 8 + co]);
    const bool hm = h > 0, hp = h < 15, wm = ww > 0, wp = ww < 15;
    for (int ci = 0; ci < 64; ++ci) {
        const float* xc = x + ci * NPOS + d * 256 + h * 16 + ww;
        float v0 = (hm && wm) ? __ldg(xc - 17) : 0.f;
        float v1 = hm        ? __ldg(xc - 16) : 0.f;
        float v2 = (hm && wp) ? __ldg(xc - 15) : 0.f;
        float v3 = wm        ? __ldg(xc - 1)  : 0.f;
        float v4 =             __ldg(xc);
        float v5 = wp        ? __ldg(xc + 1)  : 0.f;
        float v6 = (hp && wm) ? __ldg(xc + 15) : 0.f;
        float v7 = hp        ? __ldg(xc + 16) : 0.f;
        float v8 = (hp && wp) ? __ldg(xc + 17) : 0.f;
        const float* wp9 = &ws[ci * 9];
#pragma unroll
        for (int co = 0; co < 8; ++co) {
            const float* wc = wp9 + co * 576;
            acc[co] += wc[0]*v0 + wc[1]*v1 + wc[2]*v2
                     + wc[3]*v3 + wc[4]*v4 + wc[5]*v5
                     + wc[6]*v6 + wc[7]*v7 + wc[8]*v8;
        }
    }
#pragma unroll
    for (int co = 0; co < 8; ++co)
        g_y1[(cog * 8 + co) * NPOS + d * 256 + threadIdx.x] = acc[co];
}

// ---------------- conv2: 3-tap along D, pad (1,0,0) -----------------------
// grid (16 d, 8 cogroup), block 256
__global__ void k_conv_spec(const float* __restrict__ w,
                            const float* __restrict__ bias) {
    const int d = blockIdx.x, cog = blockIdx.y;
    __shared__ float ws[1536];                 // 8 co x 64 ci x 3
    for (int i = threadIdx.x; i < 1536; i += 256) ws[i] = w[cog * 1536 + i];
    __syncthreads();
    float acc[8];
#pragma unroll
    for (int co = 0; co < 8; ++co) acc[co] = __ldg(&bias[cog * 8 + co]);
    for (int ci = 0; ci < 64; ++ci) {
        const float* yc = g_y1 + ci * NPOS + d * 256 + threadIdx.x;
        float v0 = (d > 0)  ? yc[-256] : 0.f;
        float v1 = yc[0];
        float v2 = (d < 15) ? yc[256]  : 0.f;
        const float* wp3 = &ws[ci * 3];
#pragma unroll
        for (int co = 0; co < 8; ++co) {
            const float* wc = wp3 + co * 192;
            acc[co] += wc[0]*v0 + wc[1]*v1 + wc[2]*v2;
        }
    }
#pragma unroll
    for (int co = 0; co < 8; ++co)
        g_y2[(cog * 8 + co) * NPOS + d * 256 + threadIdx.x] = acc[co];
}

// ---------------- qkv 1x1 + layout transform ------------------------------
// grid (12 ocgroup-of-16, 16 poschunk), block 256
__global__ void k_qkv(const float* __restrict__ w,
                      const float* __restrict__ bias) {
    const int og  = blockIdx.x;
    const int pos = blockIdx.y * 256 + threadIdx.x;
    __shared__ float ws[1024];                 // 16 oc x 64 ci
    for (int i = threadIdx.x; i < 1024; i += 256) ws[i] = w[og * 1024 + i];
    __syncthreads();
    float acc[16];
#pragma unroll
    for (int t = 0; t < 16; ++t) acc[t] = __ldg(&bias[og * 16 + t]);
    for (int ci = 0; ci < 64; ++ci) {
        float xv = g_y2[ci * NPOS + pos];
#pragma unroll
        for (int t = 0; t < 16; ++t) acc[t] += ws[t * 64 + ci] * xv;
    }
    const int sec = og >> 2, h = og & 3;
    if (sec == 0) {                                   // Q, scaled by 1/sqrt(hd)=0.25
        float4* qp = (float4*)&g_q[(h * NPOS + pos) * 16];
#pragma unroll
        for (int t4 = 0; t4 < 4; ++t4)
            qp[t4] = make_float4(acc[t4*4+0]*0.25f, acc[t4*4+1]*0.25f,
                                 acc[t4*4+2]*0.25f, acc[t4*4+3]*0.25f);
    } else if (sec == 1) {                            // K transposed (hd-major)
#pragma unroll
        for (int t = 0; t < 16; ++t)
            g_kT[(h * 16 + t) * NPOS + pos] = acc[t];
    } else {                                          // V
        float4* vp = (float4*)&g_v[(h * NPOS + pos) * 16];
#pragma unroll
        for (int t4 = 0; t4 < 4; ++t4)
            vp[t4] = make_float4(acc[t4*4+0], acc[t4*4+1],
                                 acc[t4*4+2], acc[t4*4+3]);
    }
}

// ---------------- attention: 256 independent 16-key softmax groups --------
// grid 512: head = bx>>7, qtile(32 queries) = bx&127. block 256 = 8 key-split warps.
__global__ void __launch_bounds__(256) k_attn() {
    const int head  = blockIdx.x >> 7;
    const int qbase = (blockIdx.x & 127) * 32;
    const int warp  = threadIdx.x >> 5, lane = threadIdx.x & 31;
    __shared__ __align__(16) float Ts[256];
    __shared__ float red[8][32][16];
    Ts[threadIdx.x] = g_T[threadIdx.x];
    __syncthreads();

    const int q = qbase + lane;
    const int i = q >> 8;                              // query depth (uniform/warp)
    const float tjkL = Ts[((q >> 4) & 15) * 16 + (q & 15)] * 1.4426950408889634f;

    float qr[16];
    {
        const float4* qp = (const float4*)&g_q[(head * NPOS + q) * 16];
#pragma unroll
        for (int t = 0; t < 4; ++t) {
            float4 v = __ldg(qp + t);
            qr[t*4+0] = v.x; qr[t*4+1] = v.y; qr[t*4+2] = v.z; qr[t*4+3] = v.w;
        }
    }
    float out[16];
#pragma unroll
    for (int t = 0; t < 16; ++t) out[t] = 0.f;

    const float4* kbase = (const float4*)&g_kT[head * 16 * NPOS];
    const float4* vbase = (const float4*)&g_v [head * NPOS * 16];

    const int g0 = warp * 32;
    for (int g = g0; g < g0 + 32; ++g) {
        const int m = g >> 4, n = g & 15;
        const float4* kp = kbase + g * 4;              // +hd*1024 per hd-row
        float s[16];
#pragma unroll
        for (int o = 0; o < 16; ++o) s[o] = 0.f;
#pragma unroll
        for (int hd = 0; hd < 16; ++hd) {
            float4 a = __ldg(kp + hd * 1024 + 0);
            float4 b = __ldg(kp + hd * 1024 + 1);
            float4 c = __ldg(kp + hd * 1024 + 2);
            float4 e = __ldg(kp + hd * 1024 + 3);
            float qh = qr[hd];
            s[0] += qh*a.x;  s[1] += qh*a.y;  s[2] += qh*a.z;  s[3] += qh*a.w;
            s[4] += qh*b.x;  s[5] += qh*b.y;  s[6] += qh*b.z;  s[7] += qh*b.w;
            s[8] += qh*c.x;  s[9] += qh*c.y;  s[10]+= qh*c.z;  s[11]+= qh*c.w;
            s[12]+= qh*e.x;  s[13]+= qh*e.y;  s[14]+= qh*e.z;  s[15]+= qh*e.w;
        }
        // logits (log2 domain): s_o * g^|n-o| * (g^|i-m| g^|j-k| log2e)
        const float al = Ts[(i << 4) + m] * tjkL;
        const float4* wp = (const float4*)&Ts[n << 4];
        float wv[16];
#pragma unroll
        for (int t = 0; t < 4; ++t) {
            float4 v = wp[t];
            wv[t*4+0] = v.x; wv[t*4+1] = v.y; wv[t*4+2] = v.z; wv[t*4+3] = v.w;
        }
#pragma unroll
        for (int o = 0; o < 16; ++o) s[o] = s[o] * wv[o] * al;
        float mx = s[0];
#pragma unroll
        for (int o = 1; o < 16; ++o) mx = fmaxf(mx, s[o]);
        float sum = 0.f;
#pragma unroll
        for (int o = 0; o < 16; ++o) { float e2 = exp2f(s[o] - mx); s[o] = e2; sum += e2; }
        const float rinv = __fdividef(1.f, sum);
#pragma unroll
        for (int o = 0; o < 16; ++o) s[o] *= rinv;

        const float4* vp = vbase + (g << 6);
#pragma unroll
        for (int o = 0; o < 16; ++o) {
            float4 a = __ldg(vp + o * 4 + 0);
            float4 b = __ldg(vp + o * 4 + 1);
            float4 c = __ldg(vp + o * 4 + 2);
            float4 e = __ldg(vp + o * 4 + 3);
            float p = s[o];
            out[0] += p*a.x;  out[1] += p*a.y;  out[2] += p*a.z;  out[3] += p*a.w;
            out[4] += p*b.x;  out[5] += p*b.y;  out[6] += p*b.z;  out[7] += p*b.w;
            out[8] += p*c.x;  out[9] += p*c.y;  out[10]+= p*c.z;  out[11]+= p*c.w;
            out[12]+= p*e.x;  out[13]+= p*e.y;  out[14]+= p*e.z;  out[15]+= p*e.w;
        }
    }
    // reduce 8 key-splits
    float4* rp = (float4*)&red[warp][lane][0];
    rp[0] = make_float4(out[0],  out[1],  out[2],  out[3]);
    rp[1] = make_float4(out[4],  out[5],  out[6],  out[7]);
    rp[2] = make_float4(out[8],  out[9],  out[10], out[11]);
    rp[3] = make_float4(out[12], out[13], out[14], out[15]);
    __syncthreads();
#pragma unroll
    for (int r = 0; r < 2; ++r) {
        int e  = threadIdx.x + r * 256;
        int ql = e >> 4, hd = e & 15;
        float acc = 0.f;
#pragma unroll
        for (int w2 = 0; w2 < 8; ++w2) acc += red[w2][ql][hd];
        g_att[(head * NPOS + qbase + ql) * 16 + hd] = acc;
    }
}

// ---------------- proj 1x1 -------------------------------------------------
// grid (16 poschunk, 4 cogroup-of-16), block 256
__global__ void k_proj(const float* __restrict__ w,
                       const float* __restrict__ bias,
                       float* __restrict__ out) {
    const int pos = blockIdx.x * 256 + threadIdx.x;
    const int cog = blockIdx.y;
    __shared__ float ws[1024];                 // 16 co x 64 ci
    for (int i = threadIdx.x; i < 1024; i += 256) ws[i] = w[cog * 1024 + i];
    __syncthreads();
    float acc[16];
#pragma unroll
    for (int t = 0; t < 16; ++t) acc[t] = __ldg(&bias[cog * 16 + t]);
#pragma unroll
    for (int h = 0; h < 4; ++h) {
        const float4* ap = (const float4*)&g_att[(h * NPOS + pos) * 16];
#pragma unroll
        for (int t4 = 0; t4 < 4; ++t4) {
            float4 v = __ldg(ap + t4);
            const int ci = h * 16 + t4 * 4;
#pragma unroll
            for (int t = 0; t < 16; ++t) {
                acc[t] += ws[t * 64 + ci + 0] * v.x
                        + ws[t * 64 + ci + 1] * v.y
                        + ws[t * 64 + ci + 2] * v.z
                        + ws[t * 64 + ci + 3] * v.w;
            }
        }
    }
#pragma unroll
    for (int t = 0; t < 16; ++t)
        out[(cog * 16 + t) * NPOS + pos] = acc[t];
}

// ---------------- launch ----------------------------------------------------
extern "C" void kernel_launch(void* const* d_in, const int* in_sizes, int n_in,
                              void* d_out, int out_size) {
    const float* x      = (const float*)d_in[0];
    const float* gamma  = (const float*)d_in[1];
    const float* w_sp   = (const float*)d_in[2];
    const float* b_sp   = (const float*)d_in[3];
    const float* w_spec = (const float*)d_in[4];
    const float* b_spec = (const float*)d_in[5];
    const float* w_qkv  = (const float*)d_in[6];
    const float* b_qkv  = (const float*)d_in[7];
    const float* w_proj = (const float*)d_in[8];
    const float* b_proj = (const float*)d_in[9];
    float* out = (float*)d_out;

    k_init     <<<1, 256>>>(gamma);
    k_conv_sp  <<<dim3(16, 8), 256>>>(x, w_sp, b_sp);
    k_conv_spec<<<dim3(16, 8), 256>>>(w_spec, b_spec);
    k_qkv      <<<dim3(12, 16), 256>>>(w_qkv, b_qkv);
    k_attn     <<<512, 256>>>();
    k_proj     <<<dim3(16, 4), 256>>>(w_proj, b_proj, out);
}

// round 16
// speedup vs baseline: 1.0041x; 1.0041x over previous
#include <cuda_runtime.h>

#define NPOS 4096   // 16*16*16
#define CCH  64

// ---------------- scratch (device globals; no allocation allowed) ----------
__device__ float g_y1 [CCH*NPOS];
__device__ float g_y2 [CCH*NPOS];
__device__ float g_q  [4*NPOS*16];   // [head][pos][hd], pre-scaled by 0.25
__device__ float g_kT [4*16*NPOS];   // [head][hd][pos]
__device__ float g_v  [4*NPOS*16];   // [head][pos][hd]
__device__ float g_att[4*NPOS*16];   // attention output [head][pos][hd]
__device__ float g_T  [256];         // T[a*16+b] = sigmoid(gamma)^|a-b|

// ---------------- init: decay table --------------------------------------
__global__ void k_init(const float* __restrict__ gamma) {
    __shared__ float P[16];
    if (threadIdx.x == 0) {
        float g = 1.0f / (1.0f + expf(-gamma[0]));
        float p = 1.0f;
        for (int t = 0; t < 16; ++t) { P[t] = p; p *= g; }
    }
    __syncthreads();
    int a = threadIdx.x >> 4, b = threadIdx.x & 15;
    g_T[threadIdx.x] = P[a > b ? a - b : b - a];
}

// ---------------- conv1: 3x3 spatial, pad (0,1,1) -------------------------
// grid (16 d, 8 cogroup), block 256 = (h,w)
__global__ void k_conv_sp(const float* __restrict__ x,
                          const float* __restrict__ w,
                          const float* __restrict__ bias) {
    const int d = blockIdx.x, cog = blockIdx.y;
    __shared__ float ws[4608];                 // 8 co x 64 ci x 9
    for (int i = threadIdx.x; i < 4608; i += 256) ws[i] = w[cog * 4608 + i];
    __syncthreads();
    const int h = threadIdx.x >> 4, ww = threadIdx.x & 15;
    float acc[8];
#pragma unroll
    for (int co = 0; co < 8; ++co) acc[co] = __ldg(&bias[cog * 8 + co]);
    const bool hm = h > 0, hp = h < 15, wm = ww > 0, wp = ww < 15;
    for (int ci = 0; ci < 64; ++ci) {
        const float* xc = x + ci * NPOS + d * 256 + h * 16 + ww;
        float v0 = (hm && wm) ? __ldg(xc - 17) : 0.f;
        float v1 = hm        ? __ldg(xc - 16) : 0.f;
        float v2 = (hm && wp) ? __ldg(xc - 15) : 0.f;
        float v3 = wm        ? __ldg(xc - 1)  : 0.f;
        float v4 =             __ldg(xc);
        float v5 = wp        ? __ldg(xc + 1)  : 0.f;
        float v6 = (hp && wm) ? __ldg(xc + 15) : 0.f;
        float v7 = hp        ? __ldg(xc + 16) : 0.f;
        float v8 = (hp && wp) ? __ldg(xc + 17) : 0.f;
        const float* wp9 = &ws[ci * 9];
#pragma unroll
        for (int co = 0; co < 8; ++co) {
            const float* wc = wp9 + co * 576;
            acc[co] += wc[0]*v0 + wc[1]*v1 + wc[2]*v2
                     + wc[3]*v3 + wc[4]*v4 + wc[5]*v5
                     + wc[6]*v6 + wc[7]*v7 + wc[8]*v8;
        }
    }
#pragma unroll
    for (int co = 0; co < 8; ++co)
        g_y1[(cog * 8 + co) * NPOS + d * 256 + threadIdx.x] = acc[co];
}

// ---------------- conv2: 3-tap along D, pad (1,0,0) -----------------------
// grid (16 d, 8 cogroup), block 256
__global__ void k_conv_spec(const float* __restrict__ w,
                            const float* __restrict__ bias) {
    const int d = blockIdx.x, cog = blockIdx.y;
    __shared__ float ws[1536];                 // 8 co x 64 ci x 3
    for (int i = threadIdx.x; i < 1536; i += 256) ws[i] = w[cog * 1536 + i];
    __syncthreads();
    float acc[8];
#pragma unroll
    for (int co = 0; co < 8; ++co) acc[co] = __ldg(&bias[cog * 8 + co]);
    for (int ci = 0; ci < 64; ++ci) {
        const float* yc = g_y1 + ci * NPOS + d * 256 + threadIdx.x;
        float v0 = (d > 0)  ? yc[-256] : 0.f;
        float v1 = yc[0];
        float v2 = (d < 15) ? yc[256]  : 0.f;
        const float* wp3 = &ws[ci * 3];
#pragma unroll
        for (int co = 0; co < 8; ++co) {
            const float* wc = wp3 + co * 192;
            acc[co] += wc[0]*v0 + wc[1]*v1 + wc[2]*v2;
        }
    }
#pragma unroll
    for (int co = 0; co < 8; ++co)
        g_y2[(cog * 8 + co) * NPOS + d * 256 + threadIdx.x] = acc[co];
}

// ---------------- qkv 1x1 + layout transform ------------------------------
// grid (12 ocgroup-of-16, 16 poschunk), block 256
__global__ void k_qkv(const float* __restrict__ w,
                      const float* __restrict__ bias) {
    const int og  = blockIdx.x;
    const int pos = blockIdx.y * 256 + threadIdx.x;
    __shared__ float ws[1024];                 // 16 oc x 64 ci
    for (int i = threadIdx.x; i < 1024; i += 256) ws[i] = w[og * 1024 + i];
    __syncthreads();
    float acc[16];
#pragma unroll
    for (int t = 0; t < 16; ++t) acc[t] = __ldg(&bias[og * 16 + t]);
    for (int ci = 0; ci < 64; ++ci) {
        float xv = g_y2[ci * NPOS + pos];
#pragma unroll
        for (int t = 0; t < 16; ++t) acc[t] += ws[t * 64 + ci] * xv;
    }
    const int sec = og >> 2, h = og & 3;
    if (sec == 0) {                                   // Q, scaled by 1/sqrt(hd)=0.25
        float4* qp = (float4*)&g_q[(h * NPOS + pos) * 16];
#pragma unroll
        for (int t4 = 0; t4 < 4; ++t4)
            qp[t4] = make_float4(acc[t4*4+0]*0.25f, acc[t4*4+1]*0.25f,
                                 acc[t4*4+2]*0.25f, acc[t4*4+3]*0.25f);
    } else if (sec == 1) {                            // K transposed (hd-major)
#pragma unroll
        for (int t = 0; t < 16; ++t)
            g_kT[(h * 16 + t) * NPOS + pos] = acc[t];
    } else {                                          // V
        float4* vp = (float4*)&g_v[(h * NPOS + pos) * 16];
#pragma unroll
        for (int t4 = 0; t4 < 4; ++t4)
            vp[t4] = make_float4(acc[t4*4+0], acc[t4*4+1],
                                 acc[t4*4+2], acc[t4*4+3]);
    }
}

// ---------------- attention: 256 independent 16-key softmax groups --------
// grid 512: head = bx>>7, qtile(32 queries) = bx&127. block 256 = 8 key-split warps.
__global__ void __launch_bounds__(256) k_attn() {
    const int head  = blockIdx.x >> 7;
    const int qbase = (blockIdx.x & 127) * 32;
    const int warp  = threadIdx.x >> 5, lane = threadIdx.x & 31;
    __shared__ __align__(16) float Ts[256];
    __shared__ float red[8][32][16];
    Ts[threadIdx.x] = g_T[threadIdx.x];
    __syncthreads();

    const int q = qbase + lane;
    const int i = q >> 8;                              // query depth (uniform/warp)
    const float tjkL = Ts[((q >> 4) & 15) * 16 + (q & 15)] * 1.4426950408889634f;

    float qr[16];
    {
        const float4* qp = (const float4*)&g_q[(head * NPOS + q) * 16];
#pragma unroll
        for (int t = 0; t < 4; ++t) {
            float4 v = __ldg(qp + t);
            qr[t*4+0] = v.x; qr[t*4+1] = v.y; qr[t*4+2] = v.z; qr[t*4+3] = v.w;
        }
    }
    float out[16];
#pragma unroll
    for (int t = 0; t < 16; ++t) out[t] = 0.f;

    const float4* kbase = (const float4*)&g_kT[head * 16 * NPOS];
    const float4* vbase = (const float4*)&g_v [head * NPOS * 16];

    const int g0 = warp * 32;
    for (int g = g0; g < g0 + 32; ++g) {
        const int m = g >> 4, n = g & 15;
        const float4* kp = kbase + g * 4;              // +hd*1024 per hd-row
        float s[16];
#pragma unroll
        for (int o = 0; o < 16; ++o) s[o] = 0.f;
#pragma unroll
        for (int hd = 0; hd < 16; ++hd) {
            float4 a = __ldg(kp + hd * 1024 + 0);
            float4 b = __ldg(kp + hd * 1024 + 1);
            float4 c = __ldg(kp + hd * 1024 + 2);
            float4 e = __ldg(kp + hd * 1024 + 3);
            float qh = qr[hd];
            s[0] += qh*a.x;  s[1] += qh*a.y;  s[2] += qh*a.z;  s[3] += qh*a.w;
            s[4] += qh*b.x;  s[5] += qh*b.y;  s[6] += qh*b.z;  s[7] += qh*b.w;
            s[8] += qh*c.x;  s[9] += qh*c.y;  s[10]+= qh*c.z;  s[11]+= qh*c.w;
            s[12]+= qh*e.x;  s[13]+= qh*e.y;  s[14]+= qh*e.z;  s[15]+= qh*e.w;
        }
        // logits (log2 domain): s_o * g^|n-o| * (g^|i-m| g^|j-k| log2e)
        const float al = Ts[(i << 4) + m] * tjkL;
        const float4* wp = (const float4*)&Ts[n << 4];
        float wv[16];
#pragma unroll
        for (int t = 0; t < 4; ++t) {
            float4 v = wp[t];
            wv[t*4+0] = v.x; wv[t*4+1] = v.y; wv[t*4+2] = v.z; wv[t*4+3] = v.w;
        }
#pragma unroll
        for (int o = 0; o < 16; ++o) s[o] = s[o] * wv[o] * al;
        float mx = s[0];
#pragma unroll
        for (int o = 1; o < 16; ++o) mx = fmaxf(mx, s[o]);
        float sum = 0.f;
#pragma unroll
        for (int o = 0; o < 16; ++o) { float e2 = exp2f(s[o] - mx); s[o] = e2; sum += e2; }
        const float rinv = __fdividef(1.f, sum);
#pragma unroll
        for (int o = 0; o < 16; ++o) s[o] *= rinv;

        const float4* vp = vbase + (g << 6);
#pragma unroll
        for (int o = 0; o < 16; ++o) {
            float4 a = __ldg(vp + o * 4 + 0);
            float4 b = __ldg(vp + o * 4 + 1);
            float4 c = __ldg(vp + o * 4 + 2);
            float4 e = __ldg(vp + o * 4 + 3);
            float p = s[o];
            out[0] += p*a.x;  out[1] += p*a.y;  out[2] += p*a.z;  out[3] += p*a.w;
            out[4] += p*b.x;  out[5] += p*b.y;  out[6] += p*b.z;  out[7] += p*b.w;
            out[8] += p*c.x;  out[9] += p*c.y;  out[10]+= p*c.z;  out[11]+= p*c.w;
            out[12]+= p*e.x;  out[13]+= p*e.y;  out[14]+= p*e.z;  out[15]+= p*e.w;
        }
    }
    // reduce 8 key-splits
    float4* rp = (float4*)&red[warp][lane][0];
    rp[0] = make_float4(out[0],  out[1],  out[2],  out[3]);
    rp[1] = make_float4(out[4],  out[5],  out[6],  out[7]);
    rp[2] = make_float4(out[8],  out[9],  out[10], out[11]);
    rp[3] = make_float4(out[12], out[13], out[14], out[15]);
    __syncthreads();
#pragma unroll
    for (int r = 0; r < 2; ++r) {
        int e  = threadIdx.x + r * 256;
        int ql = e >> 4, hd = e & 15;
        float acc = 0.f;
#pragma unroll
        for (int w2 = 0; w2 < 8; ++w2) acc += red[w2][ql][hd];
        g_att[(head * NPOS + qbase + ql) * 16 + hd] = acc;
    }
}

// ---------------- proj 1x1 -------------------------------------------------
// grid (16 poschunk, 4 cogroup-of-16), block 256
__global__ void k_proj(const float* __restrict__ w,
                       const float* __restrict__ bias,
                       float* __restrict__ out) {
    const int pos = blockIdx.x * 256 + threadIdx.x;
    const int cog = blockIdx.y;
    __shared__ float ws[1024];                 // 16 co x 64 ci
    for (int i = threadIdx.x; i < 1024; i += 256) ws[i] = w[cog * 1024 + i];
    __syncthreads();
    float acc[16];
#pragma unroll
    for (int t = 0; t < 16; ++t) acc[t] = __ldg(&bias[cog * 16 + t]);
#pragma unroll
    for (int h = 0; h < 4; ++h) {
        const float4* ap = (const float4*)&g_att[(h * NPOS + pos) * 16];
#pragma unroll
        for (int t4 = 0; t4 < 4; ++t4) {
            float4 v = __ldg(ap + t4);
            const int ci = h * 16 + t4 * 4;
#pragma unroll
            for (int t = 0; t < 16; ++t) {
                acc[t] += ws[t * 64 + ci + 0] * v.x
                        + ws[t * 64 + ci + 1] * v.y
                        + ws[t * 64 + ci + 2] * v.z
                        + ws[t * 64 + ci + 3] * v.w;
            }
        }
    }
#pragma unroll
    for (int t = 0; t < 16; ++t)
        out[(cog * 16 + t) * NPOS + pos] = acc[t];
}

// ---------------- launch ----------------------------------------------------
extern "C" void kernel_launch(void* const* d_in, const int* in_sizes, int n_in,
                              void* d_out, int out_size) {
    const float* x      = (const float*)d_in[0];
    const float* gamma  = (const float*)d_in[1];
    const float* w_sp   = (const float*)d_in[2];
    const float* b_sp   = (const float*)d_in[3];
    const float* w_spec = (const float*)d_in[4];
    const float* b_spec = (const float*)d_in[5];
    const float* w_qkv  = (const float*)d_in[6];
    const float* b_qkv  = (const float*)d_in[7];
    const float* w_proj = (const float*)d_in[8];
    const float* b_proj = (const float*)d_in[9];
    float* out = (float*)d_out;

    k_init     <<<1, 256>>>(gamma);
    k_conv_sp  <<<dim3(16, 8), 256>>>(x, w_sp, b_sp);
    k_conv_spec<<<dim3(16, 8), 256>>>(w_spec, b_spec);
    k_qkv      <<<dim3(12, 16), 256>>>(w_qkv, b_qkv);
    k_attn     <<<512, 256>>>();
    k_proj     <<<dim3(16, 4), 256>>>(w_proj, b_proj, out);
}

// round 17
// speedup vs baseline: 1.0092x; 1.0051x over previous
#include <cuda_runtime.h>

#define NPOS 4096   // 16*16*16
#define CCH  64

// ---------------- scratch (device globals; no allocation allowed) ----------
__device__ float g_y1 [CCH*NPOS];
__device__ float g_y2 [CCH*NPOS];
__device__ float g_q  [4*NPOS*16];   // [head][pos][hd], pre-scaled by 0.25
__device__ float g_kT [4*16*NPOS];   // [head][hd][pos]
__device__ float g_v  [4*NPOS*16];   // [head][pos][hd]
__device__ float g_att[4*NPOS*16];   // attention output [head][pos][hd]
__device__ float g_T  [256];         // T[a*16+b] = sigmoid(gamma)^|a-b|

// ---------------- init: decay table --------------------------------------
__global__ void k_init(const float* __restrict__ gamma) {
    __shared__ float P[16];
    if (threadIdx.x == 0) {
        float g = 1.0f / (1.0f + expf(-gamma[0]));
        float p = 1.0f;
        for (int t = 0; t < 16; ++t) { P[t] = p; p *= g; }
    }
    __syncthreads();
    int a = threadIdx.x >> 4, b = threadIdx.x & 15;
    g_T[threadIdx.x] = P[a > b ? a - b : b - a];
}

// ---------------- conv1: 3x3 spatial, pad (0,1,1) -------------------------
// grid (16 d, 8 cogroup), block 256 = (h,w)
__global__ void k_conv_sp(const float* __restrict__ x,
                          const float* __restrict__ w,
                          const float* __restrict__ bias) {
    const int d = blockIdx.x, cog = blockIdx.y;
    __shared__ float ws[4608];                 // 8 co x 64 ci x 9
    for (int i = threadIdx.x; i < 4608; i += 256) ws[i] = w[cog * 4608 + i];
    __syncthreads();
    const int h = threadIdx.x >> 4, ww = threadIdx.x & 15;
    float acc[8];
#pragma unroll
    for (int co = 0; co < 8; ++co) acc[co] = __ldg(&bias[cog * 8 + co]);
    const bool hm = h > 0, hp = h < 15, wm = ww > 0, wp = ww < 15;
    for (int ci = 0; ci < 64; ++ci) {
        const float* xc = x + ci * NPOS + d * 256 + h * 16 + ww;
        float v0 = (hm && wm) ? __ldg(xc - 17) : 0.f;
        float v1 = hm        ? __ldg(xc - 16) : 0.f;
        float v2 = (hm && wp) ? __ldg(xc - 15) : 0.f;
        float v3 = wm        ? __ldg(xc - 1)  : 0.f;
        float v4 =             __ldg(xc);
        float v5 = wp        ? __ldg(xc + 1)  : 0.f;
        float v6 = (hp && wm) ? __ldg(xc + 15) : 0.f;
        float v7 = hp        ? __ldg(xc + 16) : 0.f;
        float v8 = (hp && wp) ? __ldg(xc + 17) : 0.f;
        const float* wp9 = &ws[ci * 9];
#pragma unroll
        for (int co = 0; co < 8; ++co) {
            const float* wc = wp9 + co * 576;
            acc[co] += wc[0]*v0 + wc[1]*v1 + wc[2]*v2
                     + wc[3]*v3 + wc[4]*v4 + wc[5]*v5
                     + wc[6]*v6 + wc[7]*v7 + wc[8]*v8;
        }
    }
#pragma unroll
    for (int co = 0; co < 8; ++co)
        g_y1[(cog * 8 + co) * NPOS + d * 256 + threadIdx.x] = acc[co];
}

// ---------------- conv2: 3-tap along D, pad (1,0,0) -----------------------
// grid (16 d, 8 cogroup), block 256
__global__ void k_conv_spec(const float* __restrict__ w,
                            const float* __restrict__ bias) {
    const int d = blockIdx.x, cog = blockIdx.y;
    __shared__ float ws[1536];                 // 8 co x 64 ci x 3
    for (int i = threadIdx.x; i < 1536; i += 256) ws[i] = w[cog * 1536 + i];
    __syncthreads();
    float acc[8];
#pragma unroll
    for (int co = 0; co < 8; ++co) acc[co] = __ldg(&bias[cog * 8 + co]);
    for (int ci = 0; ci < 64; ++ci) {
        const float* yc = g_y1 + ci * NPOS + d * 256 + threadIdx.x;
        float v0 = (d > 0)  ? yc[-256] : 0.f;
        float v1 = yc[0];
        float v2 = (d < 15) ? yc[256]  : 0.f;
        const float* wp3 = &ws[ci * 3];
#pragma unroll
        for (int co = 0; co < 8; ++co) {
            const float* wc = wp3 + co * 192;
            acc[co] += wc[0]*v0 + wc[1]*v1 + wc[2]*v2;
        }
    }
#pragma unroll
    for (int co = 0; co < 8; ++co)
        g_y2[(cog * 8 + co) * NPOS + d * 256 + threadIdx.x] = acc[co];
}

// ---------------- qkv 1x1 + layout transform ------------------------------
// grid (12 ocgroup-of-16, 16 poschunk), block 256
__global__ void k_qkv(const float* __restrict__ w,
                      const float* __restrict__ bias) {
    const int og  = blockIdx.x;
    const int pos = blockIdx.y * 256 + threadIdx.x;
    __shared__ float ws[1024];                 // 16 oc x 64 ci
    for (int i = threadIdx.x; i < 1024; i += 256) ws[i] = w[og * 1024 + i];
    __syncthreads();
    float acc[16];
#pragma unroll
    for (int t = 0; t < 16; ++t) acc[t] = __ldg(&bias[og * 16 + t]);
    for (int ci = 0; ci < 64; ++ci) {
        float xv = g_y2[ci * NPOS + pos];
#pragma unroll
        for (int t = 0; t < 16; ++t) acc[t] += ws[t * 64 + ci] * xv;
    }
    const int sec = og >> 2, h = og & 3;
    if (sec == 0) {                                   // Q, scaled by 1/sqrt(hd)=0.25
        float4* qp = (float4*)&g_q[(h * NPOS + pos) * 16];
#pragma unroll
        for (int t4 = 0; t4 < 4; ++t4)
            qp[t4] = make_float4(acc[t4*4+0]*0.25f, acc[t4*4+1]*0.25f,
                                 acc[t4*4+2]*0.25f, acc[t4*4+3]*0.25f);
    } else if (sec == 1) {                            // K transposed (hd-major)
#pragma unroll
        for (int t = 0; t < 16; ++t)
            g_kT[(h * 16 + t) * NPOS + pos] = acc[t];
    } else {                                          // V
        float4* vp = (float4*)&g_v[(h * NPOS + pos) * 16];
#pragma unroll
        for (int t4 = 0; t4 < 4; ++t4)
            vp[t4] = make_float4(acc[t4*4+0], acc[t4*4+1],
                                 acc[t4*4+2], acc[t4*4+3]);
    }
}

// ---------------- attention: 256 independent 16-key softmax groups --------
// grid 512: head = bx>>7, qtile(32 queries) = bx&127. block 256 = 8 key-split warps.
__global__ void __launch_bounds__(256) k_attn() {
    const int head  = blockIdx.x >> 7;
    const int qbase = (blockIdx.x & 127) * 32;
    const int warp  = threadIdx.x >> 5, lane = threadIdx.x & 31;
    __shared__ __align__(16) float Ts[256];
    __shared__ float red[8][32][16];
    Ts[threadIdx.x] = g_T[threadIdx.x];
    __syncthreads();

    const int q = qbase + lane;
    const int i = q >> 8;                              // query depth (uniform/warp)
    const float tjkL = Ts[((q >> 4) & 15) * 16 + (q & 15)] * 1.4426950408889634f;

    float qr[16];
    {
        const float4* qp = (const float4*)&g_q[(head * NPOS + q) * 16];
#pragma unroll
        for (int t = 0; t < 4; ++t) {
            float4 v = __ldg(qp + t);
            qr[t*4+0] = v.x; qr[t*4+1] = v.y; qr[t*4+2] = v.z; qr[t*4+3] = v.w;
        }
    }
    float out[16];
#pragma unroll
    for (int t = 0; t < 16; ++t) out[t] = 0.f;

    const float4* kbase = (const float4*)&g_kT[head * 16 * NPOS];
    const float4* vbase = (const float4*)&g_v [head * NPOS * 16];

    const int g0 = warp * 32;
    for (int g = g0; g < g0 + 32; ++g) {
        const int m = g >> 4, n = g & 15;
        const float4* kp = kbase + g * 4;              // +hd*1024 per hd-row
        float s[16];
#pragma unroll
        for (int o = 0; o < 16; ++o) s[o] = 0.f;
#pragma unroll
        for (int hd = 0; hd < 16; ++hd) {
            float4 a = __ldg(kp + hd * 1024 + 0);
            float4 b = __ldg(kp + hd * 1024 + 1);
            float4 c = __ldg(kp + hd * 1024 + 2);
            float4 e = __ldg(kp + hd * 1024 + 3);
            float qh = qr[hd];
            s[0] += qh*a.x;  s[1] += qh*a.y;  s[2] += qh*a.z;  s[3] += qh*a.w;
            s[4] += qh*b.x;  s[5] += qh*b.y;  s[6] += qh*b.z;  s[7] += qh*b.w;
            s[8] += qh*c.x;  s[9] += qh*c.y;  s[10]+= qh*c.z;  s[11]+= qh*c.w;
            s[12]+= qh*e.x;  s[13]+= qh*e.y;  s[14]+= qh*e.z;  s[15]+= qh*e.w;
        }
        // logits (log2 domain): s_o * g^|n-o| * (g^|i-m| g^|j-k| log2e)
        const float al = Ts[(i << 4) + m] * tjkL;
        const float4* wp = (const float4*)&Ts[n << 4];
        float wv[16];
#pragma unroll
        for (int t = 0; t < 4; ++t) {
            float4 v = wp[t];
            wv[t*4+0] = v.x; wv[t*4+1] = v.y; wv[t*4+2] = v.z; wv[t*4+3] = v.w;
        }
#pragma unroll
        for (int o = 0; o < 16; ++o) s[o] = s[o] * wv[o] * al;
        float mx = s[0];
#pragma unroll
        for (int o = 1; o < 16; ++o) mx = fmaxf(mx, s[o]);
        float sum = 0.f;
#pragma unroll
        for (int o = 0; o < 16; ++o) { float e2 = exp2f(s[o] - mx); s[o] = e2; sum += e2; }
        const float rinv = __fdividef(1.f, sum);
#pragma unroll
        for (int o = 0; o < 16; ++o) s[o] *= rinv;

        const float4* vp = vbase + (g << 6);
#pragma unroll
        for (int o = 0; o < 16; ++o) {
            float4 a = __ldg(vp + o * 4 + 0);
            float4 b = __ldg(vp + o * 4 + 1);
            float4 c = __ldg(vp + o * 4 + 2);
            float4 e = __ldg(vp + o * 4 + 3);
            float p = s[o];
            out[0] += p*a.x;  out[1] += p*a.y;  out[2] += p*a.z;  out[3] += p*a.w;
            out[4] += p*b.x;  out[5] += p*b.y;  out[6] += p*b.z;  out[7] += p*b.w;
            out[8] += p*c.x;  out[9] += p*c.y;  out[10]+= p*c.z;  out[11]+= p*c.w;
            out[12]+= p*e.x;  out[13]+= p*e.y;  out[14]+= p*e.z;  out[15]+= p*e.w;
        }
    }
    // reduce 8 key-splits
    float4* rp = (float4*)&red[warp][lane][0];
    rp[0] = make_float4(out[0],  out[1],  out[2],  out[3]);
    rp[1] = make_float4(out[4],  out[5],  out[6],  out[7]);
    rp[2] = make_float4(out[8],  out[9],  out[10], out[11]);
    rp[3] = make_float4(out[12], out[13], out[14], out[15]);
    __syncthreads();
#pragma unroll
    for (int r = 0; r < 2; ++r) {
        int e  = threadIdx.x + r * 256;
        int ql = e >> 4, hd = e & 15;
        float acc = 0.f;
#pragma unroll
        for (int w2 = 0; w2 < 8; ++w2) acc += red[w2][ql][hd];
        g_att[(head * NPOS + qbase + ql) * 16 + hd] = acc;
    }
}

// ---------------- proj 1x1 -------------------------------------------------
// grid (16 poschunk, 4 cogroup-of-16), block 256
__global__ void k_proj(const float* __restrict__ w,
                       const float* __restrict__ bias,
                       float* __restrict__ out) {
    const int pos = blockIdx.x * 256 + threadIdx.x;
    const int cog = blockIdx.y;
    __shared__ float ws[1024];                 // 16 co x 64 ci
    for (int i = threadIdx.x; i < 1024; i += 256) ws[i] = w[cog * 1024 + i];
    __syncthreads();
    float acc[16];
#pragma unroll
    for (int t = 0; t < 16; ++t) acc[t] = __ldg(&bias[cog * 16 + t]);
#pragma unroll
    for (int h = 0; h < 4; ++h) {
        const float4* ap = (const float4*)&g_att[(h * NPOS + pos) * 16];
#pragma unroll
        for (int t4 = 0; t4 < 4; ++t4) {
            float4 v = __ldg(ap + t4);
            const int ci = h * 16 + t4 * 4;
#pragma unroll
            for (int t = 0; t < 16; ++t) {
                acc[t] += ws[t * 64 + ci + 0] * v.x
                        + ws[t * 64 + ci + 1] * v.y
                        + ws[t * 64 + ci + 2] * v.z
                        + ws[t * 64 + ci + 3] * v.w;
            }
        }
    }
#pragma unroll
    for (int t = 0; t < 16; ++t)
        out[(cog * 16 + t) * NPOS + pos] = acc[t];
}

// ---------------- launch ----------------------------------------------------
extern "C" void kernel_launch(void* const* d_in, const int* in_sizes, int n_in,
                              void* d_out, int out_size) {
    const float* x      = (const float*)d_in[0];
    const float* gamma  = (const float*)d_in[1];
    const float* w_sp   = (const float*)d_in[2];
    const float* b_sp   = (const float*)d_in[3];
    const float* w_spec = (const float*)d_in[4];
    const float* b_spec = (const float*)d_in[5];
    const float* w_qkv  = (const float*)d_in[6];
    const float* b_qkv  = (const float*)d_in[7];
    const float* w_proj = (const float*)d_in[8];
    const float* b_proj = (const float*)d_in[9];
    float* out = (float*)d_out;

    k_init     <<<1, 256>>>(gamma);
    k_conv_sp  <<<dim3(16, 8), 256>>>(x, w_sp, b_sp);
    k_conv_spec<<<dim3(16, 8), 256>>>(w_spec, b_spec);
    k_qkv      <<<dim3(12, 16), 256>>>(w_qkv, b_qkv);
    k_attn     <<<512, 256>>>();
    k_proj     <<<dim3(16, 4), 256>>>(w_proj, b_proj, out);
}